// round 3
// baseline (speedup 1.0000x reference)
#include <cuda_runtime.h>
#include <cuda_bf16.h>

#define BS  16
#define NA  33600
#define NG  64
#define NC  80
#define NT1 256
#define NCHUNK ((NA + NT1 - 1) / NT1)   // 132

// ---------------- scratch (device globals; no allocation) ----------------
__device__ float  g_best[BS * NA];          // best ROUNDED iou per anchor
__device__ int    g_tgiPos[BS * NA];        // tgi | (posAny<<8)
__device__ int    g_packed[BS * NA];        // label | (mask<<8)
__device__ float  g_top3[BS * NCHUNK * 6];  // per-block top-3 fraction triples
__device__ int    g_posAnyBlk[BS * NCHUNK];
__device__ float  g_minIou[BS];             // 3rd-largest masked overlap (rounded)
__device__ int    g_needFb[BS];
__device__ int    g_lab64;                  // 1 if gt_labels is int64

// fraction compare: n1/d1 > n2/d2 for d>0
__device__ __forceinline__ bool fgt(float n1, float d1, float n2, float d2) {
    return __fmul_rn(n1, d2) > __fmul_rn(n2, d1);
}

// insert fraction into sorted triple (no index)
__device__ __forceinline__ void ins3(float n, float d,
    float& t0n, float& t0d, float& t1n, float& t1d, float& t2n, float& t2d) {
    if (fgt(n, d, t2n, t2d)) {
        if (fgt(n, d, t1n, t1d)) {
            t2n = t1n; t2d = t1d;
            if (fgt(n, d, t0n, t0d)) { t1n = t0n; t1d = t0d; t0n = n; t0d = d; }
            else                     { t1n = n;   t1d = d; }
        } else { t2n = n; t2d = d; }
    }
}

// insert fraction + index (stable: equal fractions keep earlier index first)
__device__ __forceinline__ void ins3i(float n, float d, int i,
    float& t0n, float& t0d, int& i0,
    float& t1n, float& t1d, int& i1,
    float& t2n, float& t2d, int& i2) {
    if (fgt(n, d, t2n, t2d)) {
        if (fgt(n, d, t1n, t1d)) {
            t2n = t1n; t2d = t1d; i2 = i1;
            if (fgt(n, d, t0n, t0d)) { t1n = t0n; t1d = t0d; i1 = i0; t0n = n; t0d = d; i0 = i; }
            else                     { t1n = n;   t1d = d;   i1 = i; }
        } else { t2n = n; t2d = d; i2 = i; }
    }
}

// -------------------------------- kernel 1 --------------------------------
__global__ __launch_bounds__(NT1, 4)
void k1_iou(const float4* __restrict__ pd,
            const float4* __restrict__ gt,
            const int*    __restrict__ mg) {
    __shared__ float4 sbox[NG];      // invalid GTs zeroed -> inter = 0 -> num = 0
    __shared__ float  sqa[NG];
    __shared__ float  s0n[NT1], s0d[NT1], s1n[NT1], s1d[NT1], s2n[NT1], s2d[NT1];
    __shared__ int    sAny;

    const int b   = blockIdx.y;
    const int tid = threadIdx.x;

    if (tid < NG) {
        float4 q = gt[b * NG + tid];
        if (mg[b * NG + tid] == 0) q = make_float4(0.f, 0.f, 0.f, 0.f);
        sbox[tid] = q;
        sqa[tid]  = __fmul_rn(__fsub_rn(q.z, q.x), __fsub_rn(q.w, q.y));
    }
    if (tid == 0) sAny = 0;
    __syncthreads();

    const int a = blockIdx.x * NT1 + tid;
    float t0n = -1.f, t0d = 1.f, t1n = -1.f, t1d = 1.f, t2n = -1.f, t2d = 1.f;
    int   i0 = 0, i1 = 0, i2 = 0;
    bool posAny = false;

    if (a < NA) {
        float4 p = pd[b * NA + a];
        float parea = __fmul_rn(__fsub_rn(p.z, p.x), __fsub_rn(p.w, p.y));
        #pragma unroll 8
        for (int g = 0; g < NG; g++) {
            float4 q = sbox[g];
            float iw = fmaxf(__fsub_rn(fminf(q.z, p.z), fmaxf(q.x, p.x)), 0.f);
            float ih = fmaxf(__fsub_rn(fminf(q.w, p.w), fmaxf(q.y, p.y)), 0.f);
            float num = __fmul_rn(iw, ih);        // inter (0 if invalid GT)
            float den = __fadd_rn(__fsub_rn(__fadd_rn(sqa[g], parea), num), 1e-9f);
            ins3i(num, den, g, t0n, t0d, i0, t1n, t1d, i1, t2n, t2d, i2);
        }
        // re-evaluate top-3 in the ROUNDED domain (matches reference argmax/threshold)
        float r0 = __fdiv_rn(t0n, t0d);
        float r1 = __fdiv_rn(t1n, t1d);
        float r2 = __fdiv_rn(t2n, t2d);
        float br = r0; int bi = i0;
        if (r1 > br || (r1 == br && i1 < bi)) { br = r1; bi = i1; }
        if (r2 > br || (r2 == br && i2 < bi)) { br = r2; bi = i2; }
        posAny = br > 0.3f;
        g_best[b * NA + a]   = br;
        g_tgiPos[b * NA + a] = bi | (posAny ? 0x100 : 0);
    }

    s0n[tid] = t0n; s0d[tid] = t0d;
    s1n[tid] = t1n; s1d[tid] = t1d;
    s2n[tid] = t2n; s2d[tid] = t2d;
    __syncthreads();
    if (posAny) sAny = 1;   // benign race (same value)

    for (int off = NT1 / 2; off > 0; off >>= 1) {
        if (tid < off) {
            float m0n = s0n[tid], m0d = s0d[tid], m1n = s1n[tid], m1d = s1d[tid],
                  m2n = s2n[tid], m2d = s2d[tid];
            int j = tid + off;
            ins3(s0n[j], s0d[j], m0n, m0d, m1n, m1d, m2n, m2d);
            ins3(s1n[j], s1d[j], m0n, m0d, m1n, m1d, m2n, m2d);
            ins3(s2n[j], s2d[j], m0n, m0d, m1n, m1d, m2n, m2d);
            s0n[tid] = m0n; s0d[tid] = m0d;
            s1n[tid] = m1n; s1d[tid] = m1d;
            s2n[tid] = m2n; s2d[tid] = m2d;
        }
        __syncthreads();
    }
    if (tid == 0) {
        int o = (b * NCHUNK + blockIdx.x) * 6;
        g_top3[o + 0] = s0n[0]; g_top3[o + 1] = s0d[0];
        g_top3[o + 2] = s1n[0]; g_top3[o + 3] = s1d[0];
        g_top3[o + 4] = s2n[0]; g_top3[o + 5] = s2d[0];
        g_posAnyBlk[b * NCHUNK + blockIdx.x] = sAny;
    }
}

// -------------------------------- kernel 2 --------------------------------
__global__ void k2_batch(const int* __restrict__ mg, const int* __restrict__ glRaw) {
    const int b = blockIdx.x, tid = threadIdx.x;   // 128 threads
    if (b == 0 && tid == 0) {
        // int64 little-endian labels => odd 32-bit words are all zero
        int z = glRaw[1] | glRaw[3] | glRaw[5] | glRaw[7] | glRaw[9] | glRaw[11];
        g_lab64 = (z == 0) ? 1 : 0;
    }
    float t0n = -1.f, t0d = 1.f, t1n = -1.f, t1d = 1.f, t2n = -1.f, t2d = 1.f;
    int anyP = 0;
    for (int i = tid; i < NCHUNK; i += 128) {
        const float* p = &g_top3[(b * NCHUNK + i) * 6];
        ins3(p[0], p[1], t0n, t0d, t1n, t1d, t2n, t2d);
        ins3(p[2], p[3], t0n, t0d, t1n, t1d, t2n, t2d);
        ins3(p[4], p[5], t0n, t0d, t1n, t1d, t2n, t2d);
        anyP |= g_posAnyBlk[b * NCHUNK + i];
    }
    int hv = (tid < NG) ? (mg[b * NG + tid] != 0) : 0;

    __shared__ float s0n[128], s0d[128], s1n[128], s1d[128], s2n[128], s2d[128];
    __shared__ int sA, sH;
    if (tid == 0) { sA = 0; sH = 0; }
    s0n[tid] = t0n; s0d[tid] = t0d;
    s1n[tid] = t1n; s1d[tid] = t1d;
    s2n[tid] = t2n; s2d[tid] = t2d;
    __syncthreads();
    if (anyP) sA = 1;
    if (hv)   sH = 1;
    for (int off = 64; off > 0; off >>= 1) {
        if (tid < off) {
            float m0n = s0n[tid], m0d = s0d[tid], m1n = s1n[tid], m1d = s1d[tid],
                  m2n = s2n[tid], m2d = s2d[tid];
            int j = tid + off;
            ins3(s0n[j], s0d[j], m0n, m0d, m1n, m1d, m2n, m2d);
            ins3(s1n[j], s1d[j], m0n, m0d, m1n, m1d, m2n, m2d);
            ins3(s2n[j], s2d[j], m0n, m0d, m1n, m1d, m2n, m2d);
            s0n[tid] = m0n; s0d[tid] = m0d;
            s1n[tid] = m1n; s1d[tid] = m1d;
            s2n[tid] = m2n; s2d[tid] = m2d;
        }
        __syncthreads();
    }
    if (tid == 0) {
        g_minIou[b] = __fdiv_rn(s2n[0], s2d[0]);
        g_needFb[b] = (sA == 0) && (sH != 0);
    }
}

// -------------------------------- kernel 3 --------------------------------
// ALL outputs written as float32 (harness compares a single f32-dtype concat)
__global__ void k3_final(const float4* __restrict__ gt,
                         const void* __restrict__ glRaw,
                         const int* __restrict__ mg,
                         float*  __restrict__ outLab,
                         float4* __restrict__ outBox,
                         float*  __restrict__ outFg,
                         float*  __restrict__ outTgi) {
    int idx = blockIdx.x * blockDim.x + threadIdx.x;
    if (idx >= BS * NA) return;
    int b = idx / NA;
    int tp  = g_tgiPos[idx];
    int tgi = tp & 0xFF;
    bool posAny = (tp & 0x100) != 0;
    bool fg = g_needFb[b] ? (g_best[idx] >= g_minIou[b]) : posAny;
    bool va   = mg[b * NG + tgi] != 0;
    bool mask = fg && va;
    int lab = g_lab64 ? (int)((const long long*)glRaw)[b * NG + tgi]
                      : ((const int*)glRaw)[b * NG + tgi];

    outLab[idx] = mask ? (float)lab : (float)NC;
    float4 bx = gt[b * NG + tgi];
    outBox[idx] = mask ? bx : make_float4(0.f, 0.f, 0.f, 0.f);
    outFg[idx]  = fg ? 1.f : 0.f;
    outTgi[idx] = (float)tgi;
    g_packed[idx] = lab | (mask ? 0x100 : 0);
}

// -------------------------------- kernel 4 --------------------------------
__global__ void k4_scores(float4* __restrict__ outScores) {
    int i = blockIdx.x * blockDim.x + threadIdx.x;
    if (i >= BS * NA * (NC / 4)) return;
    int anchor = i / (NC / 4);
    int c0 = (i % (NC / 4)) * 4;
    int p = g_packed[anchor];
    float4 r = make_float4(0.f, 0.f, 0.f, 0.f);
    if (p & 0x100) {
        int off = (p & 0xFF) - c0;
        if      (off == 0) r.x = 1.f;
        else if (off == 1) r.y = 1.f;
        else if (off == 2) r.z = 1.f;
        else if (off == 3) r.w = 1.f;
    }
    __stcs(&outScores[i], r);   // streaming: output never re-read
}

// ------------------------------ entry point -------------------------------
// inputs: 0 pd_scores, 1 pd_bboxes, 2 anc_points, 3 gt_labels, 4 gt_bboxes, 5 mask_gt
// output: float32 concat [labels | bboxes | scores | fg_mask | tgi], each bs*A(*k)
extern "C" void kernel_launch(void* const* d_in, const int* in_sizes, int n_in,
                              void* d_out, int out_size) {
    const float4* pd = (const float4*)d_in[1];
    const void*   gl = d_in[3];
    const float4* gt = (const float4*)d_in[4];
    const int*    mg = (const int*)d_in[5];

    float* out = (float*)d_out;
    const size_t E = (size_t)BS * NA;
    float*  outLab    = out;
    float4* outBox    = (float4*)(out + E);
    float4* outScores = (float4*)(out + E * 5);
    float*  outFg     = out + E * 85;
    float*  outTgi    = out + E * 86;

    dim3 g1(NCHUNK, BS);
    k1_iou<<<g1, NT1>>>(pd, gt, mg);
    k2_batch<<<BS, 128>>>(mg, (const int*)gl);

    int n3 = BS * NA;
    k3_final<<<(n3 + 255) / 256, 256>>>(gt, gl, mg, outLab, outBox, outFg, outTgi);

    int n4 = BS * NA * (NC / 4);
    k4_scores<<<(n4 + 255) / 256, 256>>>(outScores);
}

// round 4
// speedup vs baseline: 1.1521x; 1.1521x over previous
#include <cuda_runtime.h>
#include <cuda_bf16.h>

#define BS  16
#define NA  33600
#define NG  64
#define NC  80
#define NT1 256
#define NCHUNK 132                      // ceil(33600/256)
#define NCOMP (BS * NCHUNK)             // 2112 compute blocks
#define NBLK  (NCOMP * 3)               // 6336 total (2112 compute + 4224 zero)
#define TOT4  (BS * NA * (NC / 4))      // 10,752,000 float4 in scores region
#define ZPER  2560                      // float4 per zero block (10 iters x 256 thr)

// ---------------- scratch (device globals; no allocation) ----------------
__device__ float  g_best[BS * NA];          // best ROUNDED iou per anchor
__device__ int    g_tgiPos[BS * NA];        // tgi
__device__ int    g_packed[BS * NA];        // label | (mask<<8)  (speculative)
__device__ float  g_top3[BS * NCHUNK * 6];  // per-block top-3 fraction triples
__device__ int    g_posAnyBlk[BS * NCHUNK];
__device__ float  g_minIou[BS];             // 3rd-largest masked overlap (rounded)
__device__ int    g_needFb[BS];
__device__ int    g_lab64;                  // 1 if gt_labels is int64

// fraction compare: n1/d1 > n2/d2 for d>0
__device__ __forceinline__ bool fgt(float n1, float d1, float n2, float d2) {
    return __fmul_rn(n1, d2) > __fmul_rn(n2, d1);
}

__device__ __forceinline__ void ins3(float n, float d,
    float& t0n, float& t0d, float& t1n, float& t1d, float& t2n, float& t2d) {
    if (fgt(n, d, t2n, t2d)) {
        if (fgt(n, d, t1n, t1d)) {
            t2n = t1n; t2d = t1d;
            if (fgt(n, d, t0n, t0d)) { t1n = t0n; t1d = t0d; t0n = n; t0d = d; }
            else                     { t1n = n;   t1d = d; }
        } else { t2n = n; t2d = d; }
    }
}

__device__ __forceinline__ void ins3i(float n, float d, int i,
    float& t0n, float& t0d, int& i0,
    float& t1n, float& t1d, int& i1,
    float& t2n, float& t2d, int& i2) {
    if (fgt(n, d, t2n, t2d)) {
        if (fgt(n, d, t1n, t1d)) {
            t2n = t1n; t2d = t1d; i2 = i1;
            if (fgt(n, d, t0n, t0d)) { t1n = t0n; t1d = t0d; i1 = i0; t0n = n; t0d = d; i0 = i; }
            else                     { t1n = n;   t1d = d;   i1 = i; }
        } else { t2n = n; t2d = d; i2 = i; }
    }
}

// ---------------- fused kernel: k1 compute blocks + scores zero-fill ------
__global__ __launch_bounds__(NT1)
void k1f(const float4* __restrict__ pd,
         const float4* __restrict__ gt,
         const int*    __restrict__ mg,
         const int*    __restrict__ glRaw,
         float*  __restrict__ outLab,
         float4* __restrict__ outBox,
         float*  __restrict__ outFg,
         float*  __restrict__ outTgi,
         float4* __restrict__ outScores4) {
    const int bid = blockIdx.x;
    const int tid = threadIdx.x;

    if (bid % 3 != 2) {
        // -------- zero-fill role: streaming stores, no dependency --------
        int zb = bid - bid / 3;                       // 0..4223
        size_t base = (size_t)zb * ZPER + tid;
        const float4 z4 = make_float4(0.f, 0.f, 0.f, 0.f);
        #pragma unroll
        for (int i = 0; i < ZPER / NT1; i++) {
            size_t idx = base + (size_t)i * NT1;
            if (idx < (size_t)TOT4) __stcs(&outScores4[idx], z4);
        }
        return;
    }

    // ------------------------- compute role (k1) -------------------------
    const int cb    = bid / 3;          // 0..2111
    const int b     = cb / NCHUNK;
    const int chunk = cb % NCHUNK;

    __shared__ float4 sbox[NG];         // invalid GTs zeroed -> inter = 0
    __shared__ float  sqa[NG];
    __shared__ int    svalid[NG];
    __shared__ int    slab[NG];
    __shared__ float  s0n[NT1], s0d[NT1], s1n[NT1], s1d[NT1], s2n[NT1], s2d[NT1];
    __shared__ int    sAny;

    if (tid < NG) {
        // label dtype detection (int64 LE => odd 32-bit words zero)
        int z = glRaw[1] | glRaw[3] | glRaw[5] | glRaw[7] | glRaw[9] | glRaw[11];
        bool l64 = (z == 0);
        int v = mg[b * NG + tid];
        float4 q = gt[b * NG + tid];
        if (v == 0) q = make_float4(0.f, 0.f, 0.f, 0.f);
        sbox[tid]   = q;
        sqa[tid]    = __fmul_rn(__fsub_rn(q.z, q.x), __fsub_rn(q.w, q.y));
        svalid[tid] = v;
        slab[tid]   = l64 ? (int)((const long long*)glRaw)[b * NG + tid]
                          : glRaw[b * NG + tid];
    }
    if (tid == 0) sAny = 0;
    __syncthreads();

    const int a = chunk * NT1 + tid;
    float t0n = -1.f, t0d = 1.f, t1n = -1.f, t1d = 1.f, t2n = -1.f, t2d = 1.f;
    int   i0 = 0, i1 = 0, i2 = 0;
    bool posAny = false;

    if (a < NA) {
        float4 p = pd[b * NA + a];
        float parea = __fmul_rn(__fsub_rn(p.z, p.x), __fsub_rn(p.w, p.y));
        #pragma unroll 8
        for (int g = 0; g < NG; g++) {
            float4 q = sbox[g];
            float iw = fmaxf(__fsub_rn(fminf(q.z, p.z), fmaxf(q.x, p.x)), 0.f);
            float ih = fmaxf(__fsub_rn(fminf(q.w, p.w), fmaxf(q.y, p.y)), 0.f);
            float num = __fmul_rn(iw, ih);
            float den = __fadd_rn(__fsub_rn(__fadd_rn(sqa[g], parea), num), 1e-9f);
            ins3i(num, den, g, t0n, t0d, i0, t1n, t1d, i1, t2n, t2d, i2);
        }
        // rounded-domain re-evaluation (matches reference argmax/threshold)
        float r0 = __fdiv_rn(t0n, t0d);
        float r1 = __fdiv_rn(t1n, t1d);
        float r2 = __fdiv_rn(t2n, t2d);
        float br = r0; int bi = i0;
        if (r1 > br || (r1 == br && i1 < bi)) { br = r1; bi = i1; }
        if (r2 > br || (r2 == br && i2 < bi)) { br = r2; bi = i2; }
        posAny = br > 0.3f;

        const int idx = b * NA + a;
        bool va   = svalid[bi] != 0;
        bool mask = posAny && va;          // speculative (valid when !need_fb)
        int  lab  = slab[bi];

        outLab[idx] = mask ? (float)lab : (float)NC;
        float4 bx = sbox[bi];              // zeroed when invalid; mask guards
        outBox[idx] = mask ? bx : make_float4(0.f, 0.f, 0.f, 0.f);
        outFg[idx]  = posAny ? 1.f : 0.f;
        outTgi[idx] = (float)bi;

        g_best[idx]   = br;
        g_tgiPos[idx] = bi;
        g_packed[idx] = lab | (mask ? 0x100 : 0);
    }

    s0n[tid] = t0n; s0d[tid] = t0d;
    s1n[tid] = t1n; s1d[tid] = t1d;
    s2n[tid] = t2n; s2d[tid] = t2d;
    __syncthreads();
    if (posAny) sAny = 1;   // benign race (same value)

    for (int off = NT1 / 2; off > 0; off >>= 1) {
        if (tid < off) {
            float m0n = s0n[tid], m0d = s0d[tid], m1n = s1n[tid], m1d = s1d[tid],
                  m2n = s2n[tid], m2d = s2d[tid];
            int j = tid + off;
            ins3(s0n[j], s0d[j], m0n, m0d, m1n, m1d, m2n, m2d);
            ins3(s1n[j], s1d[j], m0n, m0d, m1n, m1d, m2n, m2d);
            ins3(s2n[j], s2d[j], m0n, m0d, m1n, m1d, m2n, m2d);
            s0n[tid] = m0n; s0d[tid] = m0d;
            s1n[tid] = m1n; s1d[tid] = m1d;
            s2n[tid] = m2n; s2d[tid] = m2d;
        }
        __syncthreads();
    }
    if (tid == 0) {
        int o = (b * NCHUNK + chunk) * 6;
        g_top3[o + 0] = s0n[0]; g_top3[o + 1] = s0d[0];
        g_top3[o + 2] = s1n[0]; g_top3[o + 3] = s1d[0];
        g_top3[o + 4] = s2n[0]; g_top3[o + 5] = s2d[0];
        g_posAnyBlk[b * NCHUNK + chunk] = sAny;
    }
}

// -------------------------------- kernel 2 --------------------------------
__global__ void k2_batch(const int* __restrict__ mg, const int* __restrict__ glRaw) {
    const int b = blockIdx.x, tid = threadIdx.x;   // 128 threads
    if (b == 0 && tid == 0) {
        int z = glRaw[1] | glRaw[3] | glRaw[5] | glRaw[7] | glRaw[9] | glRaw[11];
        g_lab64 = (z == 0) ? 1 : 0;
    }
    float t0n = -1.f, t0d = 1.f, t1n = -1.f, t1d = 1.f, t2n = -1.f, t2d = 1.f;
    int anyP = 0;
    for (int i = tid; i < NCHUNK; i += 128) {
        const float* p = &g_top3[(b * NCHUNK + i) * 6];
        ins3(p[0], p[1], t0n, t0d, t1n, t1d, t2n, t2d);
        ins3(p[2], p[3], t0n, t0d, t1n, t1d, t2n, t2d);
        ins3(p[4], p[5], t0n, t0d, t1n, t1d, t2n, t2d);
        anyP |= g_posAnyBlk[b * NCHUNK + i];
    }
    int hv = (tid < NG) ? (mg[b * NG + tid] != 0) : 0;

    __shared__ float s0n[128], s0d[128], s1n[128], s1d[128], s2n[128], s2d[128];
    __shared__ int sA, sH;
    if (tid == 0) { sA = 0; sH = 0; }
    s0n[tid] = t0n; s0d[tid] = t0d;
    s1n[tid] = t1n; s1d[tid] = t1d;
    s2n[tid] = t2n; s2d[tid] = t2d;
    __syncthreads();
    if (anyP) sA = 1;
    if (hv)   sH = 1;
    for (int off = 64; off > 0; off >>= 1) {
        if (tid < off) {
            float m0n = s0n[tid], m0d = s0d[tid], m1n = s1n[tid], m1d = s1d[tid],
                  m2n = s2n[tid], m2d = s2d[tid];
            int j = tid + off;
            ins3(s0n[j], s0d[j], m0n, m0d, m1n, m1d, m2n, m2d);
            ins3(s1n[j], s1d[j], m0n, m0d, m1n, m1d, m2n, m2d);
            ins3(s2n[j], s2d[j], m0n, m0d, m1n, m1d, m2n, m2d);
            s0n[tid] = m0n; s0d[tid] = m0d;
            s1n[tid] = m1n; s1d[tid] = m1d;
            s2n[tid] = m2n; s2d[tid] = m2d;
        }
        __syncthreads();
    }
    if (tid == 0) {
        g_minIou[b] = __fdiv_rn(s2n[0], s2d[0]);
        g_needFb[b] = (sA == 0) && (sH != 0);
    }
}

// ------------- k3fix: scatter one-hot; full rewrite only if need_fb -------
__global__ void k3fix(const float4* __restrict__ gt,
                      const int* __restrict__ glRaw,
                      const int* __restrict__ mg,
                      float*  __restrict__ outLab,
                      float4* __restrict__ outBox,
                      float*  __restrict__ outFg,
                      float*  __restrict__ outTgi,
                      float*  __restrict__ outScores) {
    int idx = blockIdx.x * blockDim.x + threadIdx.x;
    if (idx >= BS * NA) return;
    int b = idx / NA;

    if (!g_needFb[b]) {
        // fast path: speculative outputs already correct; just scatter ones
        int p = g_packed[idx];
        if (p & 0x100) outScores[(size_t)idx * NC + (p & 0xFF)] = 1.f;
        return;
    }
    // fallback: recompute this batch's outputs with fallback fg
    int  tgi  = g_tgiPos[idx];
    bool fg   = g_best[idx] >= g_minIou[b];
    bool va   = mg[b * NG + tgi] != 0;
    bool mask = fg && va;
    int  lab  = g_lab64 ? (int)((const long long*)glRaw)[b * NG + tgi]
                        : glRaw[b * NG + tgi];

    outLab[idx] = mask ? (float)lab : (float)NC;
    float4 bx = gt[b * NG + tgi];
    outBox[idx] = mask ? bx : make_float4(0.f, 0.f, 0.f, 0.f);
    outFg[idx]  = fg ? 1.f : 0.f;
    outTgi[idx] = (float)tgi;
    if (mask) outScores[(size_t)idx * NC + lab] = 1.f;
}

// ------------------------------ entry point -------------------------------
// inputs: 0 pd_scores, 1 pd_bboxes, 2 anc_points, 3 gt_labels, 4 gt_bboxes, 5 mask_gt
// output: float32 concat [labels | bboxes | scores | fg_mask | tgi]
extern "C" void kernel_launch(void* const* d_in, const int* in_sizes, int n_in,
                              void* d_out, int out_size) {
    const float4* pd = (const float4*)d_in[1];
    const int*    gl = (const int*)d_in[3];
    const float4* gt = (const float4*)d_in[4];
    const int*    mg = (const int*)d_in[5];

    float* out = (float*)d_out;
    const size_t E = (size_t)BS * NA;
    float*  outLab    = out;
    float4* outBox    = (float4*)(out + E);
    float*  outScores = out + E * 5;
    float*  outFg     = out + E * 85;
    float*  outTgi    = out + E * 86;

    k1f<<<NBLK, NT1>>>(pd, gt, mg, gl, outLab, outBox, outFg, outTgi,
                       (float4*)outScores);
    k2_batch<<<BS, 128>>>(mg, gl);

    int n3 = BS * NA;
    k3fix<<<(n3 + 255) / 256, 256>>>(gt, gl, mg, outLab, outBox, outFg, outTgi,
                                     outScores);
}

// round 5
// speedup vs baseline: 1.4706x; 1.2764x over previous
#include <cuda_runtime.h>
#include <cuda_bf16.h>

#define BS  16
#define NA  33600
#define NG  64
#define NC  80
#define NT1 256
#define NCHUNK 132                      // ceil(33600/256)
#define NCOMP (BS * NCHUNK)             // 2112 compute blocks
#define NBLK  (NCOMP * 3)               // 6336 total (2112 compute + 4224 zero)
#define TOT4  (BS * NA * (NC / 4))      // 10,752,000 float4 in scores region
#define ZPER  2560                      // float4 per zero block

// ---------------- scratch (device globals; no allocation) ----------------
__device__ float  g_best[BS * NA];          // best ROUNDED iou per anchor
__device__ int    g_tgiPos[BS * NA];        // tgi
__device__ int    g_packed[BS * NA];        // label | (mask<<8)  (speculative)
__device__ float  g_top3[BS * NCHUNK * 6];  // per-block top-3 (fallback only)
__device__ int    g_posAnyBlk[BS * NCHUNK];
__device__ float  g_minIou[BS];
__device__ int    g_needFb[BS];
__device__ int    g_lab64;

__device__ __forceinline__ bool fgt(float n1, float d1, float n2, float d2) {
    return __fmul_rn(n1, d2) > __fmul_rn(n2, d1);
}

__device__ __forceinline__ void ins3(float n, float d,
    float& t0n, float& t0d, float& t1n, float& t1d, float& t2n, float& t2d) {
    if (fgt(n, d, t2n, t2d)) {
        if (fgt(n, d, t1n, t1d)) {
            t2n = t1n; t2d = t1d;
            if (fgt(n, d, t0n, t0d)) { t1n = t0n; t1d = t0d; t0n = n; t0d = d; }
            else                     { t1n = n;   t1d = d; }
        } else { t2n = n; t2d = d; }
    }
}

// ---------------- fused kernel: compute blocks + scores zero-fill ---------
__global__ __launch_bounds__(NT1)
void k1f(const float4* __restrict__ pd,
         const float4* __restrict__ gt,
         const int*    __restrict__ mg,
         const int*    __restrict__ glRaw,
         float*  __restrict__ outLab,
         float4* __restrict__ outBox,
         float*  __restrict__ outFg,
         float*  __restrict__ outTgi,
         float4* __restrict__ outScores4) {
    const int bid = blockIdx.x;
    const int tid = threadIdx.x;

    if (bid % 3 != 2) {
        // -------- zero-fill role: pure streaming stores --------
        int zb = bid - bid / 3;                       // 0..4223
        size_t base = (size_t)zb * ZPER + tid;
        const float4 z4 = make_float4(0.f, 0.f, 0.f, 0.f);
        #pragma unroll
        for (int i = 0; i < ZPER / NT1; i++) {
            size_t idx = base + (size_t)i * NT1;
            if (idx < (size_t)TOT4) __stcs(&outScores4[idx], z4);
        }
        return;
    }

    // ------------------------- compute role -------------------------
    const int cb    = bid / 3;
    const int b     = cb / NCHUNK;
    const int chunk = cb % NCHUNK;

    __shared__ float4 sboxc[NG];     // compacted valid boxes
    __shared__ float  sareac[NG];    // compacted gt areas
    __shared__ int    sgidxc[NG];    // compacted -> original index
    __shared__ float4 sbox0[NG];     // original boxes (output lookup)
    __shared__ int    slab[NG];
    __shared__ int    svalid[NG];
    __shared__ int    scnt[2];
    __shared__ int    snv, sAny, sl64;

    int v = 0; unsigned bm = 0; float4 q;
    if (tid < NG) {
        v = mg[b * NG + tid];
        q = gt[b * NG + tid];
        bm = __ballot_sync(0xffffffffu, v != 0);
        if ((tid & 31) == 0) scnt[tid >> 5] = __popc(bm);
        sbox0[tid]  = q;
        svalid[tid] = v;
    }
    if (tid == 0) {
        sAny = 0;
        sl64 = ((glRaw[1] | glRaw[3] | glRaw[5] | glRaw[7] | glRaw[9] | glRaw[11]) == 0);
    }
    __syncthreads();

    if (tid < NG) {
        slab[tid] = sl64 ? (int)((const long long*)glRaw)[b * NG + tid]
                         : glRaw[b * NG + tid];
        if (v) {
            int pos = __popc(bm & ((1u << (tid & 31)) - 1)) + ((tid >= 32) ? scnt[0] : 0);
            sboxc[pos]  = q;
            sareac[pos] = __fmul_rn(__fsub_rn(q.z, q.x), __fsub_rn(q.w, q.y));
            sgidxc[pos] = tid;
        }
        if (tid == 0) snv = scnt[0] + scnt[1];
    }
    __syncthreads();

    const int a = chunk * NT1 + tid;
    bool posAny = false;

    if (a < NA) {
        float4 p = pd[b * NA + a];
        float parea = __fmul_rn(__fsub_rn(p.z, p.x), __fsub_rn(p.w, p.y));
        float b0n = 0.f, b0d = 1.f, b1n = 0.f, b1d = 1.f;
        int   i0 = 0, i1 = 0;
        const int nv = snv;
        #pragma unroll 4
        for (int j = 0; j < nv; j++) {
            float4 qq = sboxc[j];
            float iw = fmaxf(__fsub_rn(fminf(qq.z, p.z), fmaxf(qq.x, p.x)), 0.f);
            float ih = fmaxf(__fsub_rn(fminf(qq.w, p.w), fmaxf(qq.y, p.y)), 0.f);
            float num = __fmul_rn(iw, ih);
            float den = __fadd_rn(__fsub_rn(__fadd_rn(sareac[j], parea), num), 1e-9f);
            if (__fmul_rn(num, b1d) > __fmul_rn(b1n, den)) {     // beats 2nd
                int g = sgidxc[j];
                if (__fmul_rn(num, b0d) > __fmul_rn(b0n, den)) {
                    b1n = b0n; b1d = b0d; i1 = i0;
                    b0n = num; b0d = den; i0 = g;
                } else {
                    b1n = num; b1d = den; i1 = g;
                }
            }
        }
        // rounded-domain re-evaluation (matches reference argmax/threshold)
        float r0 = __fdiv_rn(b0n, b0d);
        float r1 = __fdiv_rn(b1n, b1d);
        int bi = i0;
        if (r1 == r0 && i1 < i0) bi = i1;
        posAny = r0 > 0.3f;

        const int idx = b * NA + a;
        bool mask = posAny && (svalid[bi] != 0);
        int  lab  = slab[bi];

        outLab[idx] = mask ? (float)lab : (float)NC;
        float4 bx = sbox0[bi];
        outBox[idx] = mask ? bx : make_float4(0.f, 0.f, 0.f, 0.f);
        outFg[idx]  = posAny ? 1.f : 0.f;
        outTgi[idx] = (float)bi;

        g_best[idx]   = r0;
        g_tgiPos[idx] = bi;
        g_packed[idx] = lab | (mask ? 0x100 : 0);
        if (posAny) sAny = 1;   // benign race
    }
    __syncthreads();
    if (tid == 0) g_posAnyBlk[b * NCHUNK + chunk] = sAny;
}

// ---------------- k2: need_fb decision only -------------------------------
__global__ void k2_batch(const int* __restrict__ mg, const int* __restrict__ glRaw) {
    const int b = blockIdx.x, tid = threadIdx.x;   // 128 threads
    if (b == 0 && tid == 0) {
        int z = glRaw[1] | glRaw[3] | glRaw[5] | glRaw[7] | glRaw[9] | glRaw[11];
        g_lab64 = (z == 0) ? 1 : 0;
    }
    int anyP = 0;
    for (int i = tid; i < NCHUNK; i += 128) anyP |= g_posAnyBlk[b * NCHUNK + i];
    int hv = (tid < NG) ? (mg[b * NG + tid] != 0) : 0;
    __shared__ int sA, sH;
    if (tid == 0) { sA = 0; sH = 0; }
    __syncthreads();
    if (anyP) sA = 1;
    if (hv)   sH = 1;
    __syncthreads();
    if (tid == 0) g_needFb[b] = (sA == 0) && (sH != 0);
}

// ---------------- fallback pass 1: per-block top-3 (flagged batches only) --
__global__ __launch_bounds__(NT1)
void k_fb1(const float4* __restrict__ pd,
           const float4* __restrict__ gt,
           const int*    __restrict__ mg) {
    const int b = blockIdx.y;
    if (!g_needFb[b]) return;
    const int tid = threadIdx.x;

    __shared__ float4 sbox[NG];
    __shared__ float  sqa[NG];
    __shared__ float  s0n[NT1], s0d[NT1], s1n[NT1], s1d[NT1], s2n[NT1], s2d[NT1];

    if (tid < NG) {
        float4 q = gt[b * NG + tid];
        if (mg[b * NG + tid] == 0) q = make_float4(0.f, 0.f, 0.f, 0.f);
        sbox[tid] = q;
        sqa[tid]  = __fmul_rn(__fsub_rn(q.z, q.x), __fsub_rn(q.w, q.y));
    }
    __syncthreads();

    const int a = blockIdx.x * NT1 + tid;
    float t0n = -1.f, t0d = 1.f, t1n = -1.f, t1d = 1.f, t2n = -1.f, t2d = 1.f;
    if (a < NA) {
        float4 p = pd[b * NA + a];
        float parea = __fmul_rn(__fsub_rn(p.z, p.x), __fsub_rn(p.w, p.y));
        #pragma unroll 8
        for (int g = 0; g < NG; g++) {
            float4 q = sbox[g];
            float iw = fmaxf(__fsub_rn(fminf(q.z, p.z), fmaxf(q.x, p.x)), 0.f);
            float ih = fmaxf(__fsub_rn(fminf(q.w, p.w), fmaxf(q.y, p.y)), 0.f);
            float num = __fmul_rn(iw, ih);
            float den = __fadd_rn(__fsub_rn(__fadd_rn(sqa[g], parea), num), 1e-9f);
            ins3(num, den, t0n, t0d, t1n, t1d, t2n, t2d);
        }
    }
    s0n[tid] = t0n; s0d[tid] = t0d;
    s1n[tid] = t1n; s1d[tid] = t1d;
    s2n[tid] = t2n; s2d[tid] = t2d;
    __syncthreads();
    for (int off = NT1 / 2; off > 0; off >>= 1) {
        if (tid < off) {
            float m0n = s0n[tid], m0d = s0d[tid], m1n = s1n[tid], m1d = s1d[tid],
                  m2n = s2n[tid], m2d = s2d[tid];
            int j = tid + off;
            ins3(s0n[j], s0d[j], m0n, m0d, m1n, m1d, m2n, m2d);
            ins3(s1n[j], s1d[j], m0n, m0d, m1n, m1d, m2n, m2d);
            ins3(s2n[j], s2d[j], m0n, m0d, m1n, m1d, m2n, m2d);
            s0n[tid] = m0n; s0d[tid] = m0d;
            s1n[tid] = m1n; s1d[tid] = m1d;
            s2n[tid] = m2n; s2d[tid] = m2d;
        }
        __syncthreads();
    }
    if (tid == 0) {
        int o = (b * NCHUNK + blockIdx.x) * 6;
        g_top3[o + 0] = s0n[0]; g_top3[o + 1] = s0d[0];
        g_top3[o + 2] = s1n[0]; g_top3[o + 3] = s1d[0];
        g_top3[o + 4] = s2n[0]; g_top3[o + 5] = s2d[0];
    }
}

// ---------------- fallback pass 2: merge -> min_iou ------------------------
__global__ void k_fb2() {
    const int b = blockIdx.x, tid = threadIdx.x;   // 128 threads
    if (!g_needFb[b]) return;
    float t0n = -1.f, t0d = 1.f, t1n = -1.f, t1d = 1.f, t2n = -1.f, t2d = 1.f;
    for (int i = tid; i < NCHUNK; i += 128) {
        const float* p = &g_top3[(b * NCHUNK + i) * 6];
        ins3(p[0], p[1], t0n, t0d, t1n, t1d, t2n, t2d);
        ins3(p[2], p[3], t0n, t0d, t1n, t1d, t2n, t2d);
        ins3(p[4], p[5], t0n, t0d, t1n, t1d, t2n, t2d);
    }
    __shared__ float s0n[128], s0d[128], s1n[128], s1d[128], s2n[128], s2d[128];
    s0n[tid] = t0n; s0d[tid] = t0d;
    s1n[tid] = t1n; s1d[tid] = t1d;
    s2n[tid] = t2n; s2d[tid] = t2d;
    __syncthreads();
    for (int off = 64; off > 0; off >>= 1) {
        if (tid < off) {
            float m0n = s0n[tid], m0d = s0d[tid], m1n = s1n[tid], m1d = s1d[tid],
                  m2n = s2n[tid], m2d = s2d[tid];
            int j = tid + off;
            ins3(s0n[j], s0d[j], m0n, m0d, m1n, m1d, m2n, m2d);
            ins3(s1n[j], s1d[j], m0n, m0d, m1n, m1d, m2n, m2d);
            ins3(s2n[j], s2d[j], m0n, m0d, m1n, m1d, m2n, m2d);
            s0n[tid] = m0n; s0d[tid] = m0d;
            s1n[tid] = m1n; s1d[tid] = m1d;
            s2n[tid] = m2n; s2d[tid] = m2d;
        }
        __syncthreads();
    }
    if (tid == 0) g_minIou[b] = __fdiv_rn(s2n[0], s2d[0]);
}

// ---------------- k3fix: scatter ones; full rewrite only if need_fb --------
__global__ void k3fix(const float4* __restrict__ gt,
                      const int* __restrict__ glRaw,
                      const int* __restrict__ mg,
                      float*  __restrict__ outLab,
                      float4* __restrict__ outBox,
                      float*  __restrict__ outFg,
                      float*  __restrict__ outTgi,
                      float*  __restrict__ outScores) {
    int idx = blockIdx.x * blockDim.x + threadIdx.x;
    if (idx >= BS * NA) return;
    int b = idx / NA;

    if (!g_needFb[b]) {
        int p = g_packed[idx];
        if (p & 0x100) outScores[(size_t)idx * NC + (p & 0xFF)] = 1.f;
        return;
    }
    int  tgi  = g_tgiPos[idx];
    bool fg   = g_best[idx] >= g_minIou[b];
    bool va   = mg[b * NG + tgi] != 0;
    bool mask = fg && va;
    int  lab  = g_lab64 ? (int)((const long long*)glRaw)[b * NG + tgi]
                        : glRaw[b * NG + tgi];

    outLab[idx] = mask ? (float)lab : (float)NC;
    float4 bx = gt[b * NG + tgi];
    outBox[idx] = mask ? bx : make_float4(0.f, 0.f, 0.f, 0.f);
    outFg[idx]  = fg ? 1.f : 0.f;
    outTgi[idx] = (float)tgi;
    if (mask) outScores[(size_t)idx * NC + lab] = 1.f;
}

// ------------------------------ entry point -------------------------------
extern "C" void kernel_launch(void* const* d_in, const int* in_sizes, int n_in,
                              void* d_out, int out_size) {
    const float4* pd = (const float4*)d_in[1];
    const int*    gl = (const int*)d_in[3];
    const float4* gt = (const float4*)d_in[4];
    const int*    mg = (const int*)d_in[5];

    float* out = (float*)d_out;
    const size_t E = (size_t)BS * NA;
    float*  outLab    = out;
    float4* outBox    = (float4*)(out + E);
    float*  outScores = out + E * 5;
    float*  outFg     = out + E * 85;
    float*  outTgi    = out + E * 86;

    k1f<<<NBLK, NT1>>>(pd, gt, mg, gl, outLab, outBox, outFg, outTgi,
                       (float4*)outScores);
    k2_batch<<<BS, 128>>>(mg, gl);

    dim3 gfb(NCHUNK, BS);
    k_fb1<<<gfb, NT1>>>(pd, gt, mg);
    k_fb2<<<BS, 128>>>();

    int n3 = BS * NA;
    k3fix<<<(n3 + 255) / 256, 256>>>(gt, gl, mg, outLab, outBox, outFg, outTgi,
                                     outScores);
}

// round 6
// speedup vs baseline: 1.7355x; 1.1801x over previous
#include <cuda_runtime.h>
#include <cstdint>

#define BS  16
#define NA  33600
#define NG  64
#define NC  80
#define NT1 256
#define NCHUNK 132                      // ceil(33600/256); last chunk has 64 anchors
#define NCOMP (BS * NCHUNK)             // 2112 compute blocks

// ---------------- scratch (device globals; no allocation) ----------------
__device__ int    g_posAnyBlk[BS * NCHUNK];
__device__ float  g_top3[BS * NCHUNK * 6];  // fallback only
__device__ float  g_minIou[BS];
__device__ int    g_needFb[BS];
__device__ int    g_lab64;

__device__ __forceinline__ bool fgt(float n1, float d1, float n2, float d2) {
    return __fmul_rn(n1, d2) > __fmul_rn(n2, d1);
}

__device__ __forceinline__ void ins3(float n, float d,
    float& t0n, float& t0d, float& t1n, float& t1d, float& t2n, float& t2d) {
    if (fgt(n, d, t2n, t2d)) {
        if (fgt(n, d, t1n, t1d)) {
            t2n = t1n; t2d = t1d;
            if (fgt(n, d, t0n, t0d)) { t1n = t0n; t1d = t0d; t0n = n; t0d = d; }
            else                     { t1n = n;   t1d = d; }
        } else { t2n = n; t2d = d; }
    }
}

// ================= main fused kernel: compute + ALL output writes =========
__global__ __launch_bounds__(NT1)
void k1f(const float4* __restrict__ pd,
         const float4* __restrict__ gt,
         const int*    __restrict__ mg,
         const int*    __restrict__ glRaw,
         float*  __restrict__ outLab,
         float4* __restrict__ outBox,
         float*  __restrict__ outFg,
         float*  __restrict__ outTgi,
         float*  __restrict__ outScores) {
    __shared__ float4 sboxc[NG];     // compacted valid boxes
    __shared__ float  sareac[NG];
    __shared__ int    sgidxc[NG];
    __shared__ float4 sbox0[NG];     // original boxes
    __shared__ int    slab[NG];
    __shared__ int    svalid[NG];
    __shared__ int    spacked[NT1];  // per-anchor lab | mask<<8
    __shared__ int    scnt[2];
    __shared__ int    snv, sl64;
    __shared__ __align__(16) float sbuf[2][64 * NC];   // 2 x 20 KB staging

    const int cb    = blockIdx.x;
    const int b     = cb / NCHUNK;
    const int chunk = cb % NCHUNK;
    const int tid   = threadIdx.x;

    int v = 0; unsigned bm = 0; float4 q;
    if (tid < NG) {
        v = mg[b * NG + tid];
        q = gt[b * NG + tid];
        bm = __ballot_sync(0xffffffffu, v != 0);
        if ((tid & 31) == 0) scnt[tid >> 5] = __popc(bm);
        sbox0[tid]  = q;
        svalid[tid] = v;
    }
    if (tid == 0)
        sl64 = ((glRaw[1] | glRaw[3] | glRaw[5] | glRaw[7] | glRaw[9] | glRaw[11]) == 0);
    spacked[tid] = 0;

    // zero both staging buffers (2560 float4, 10 per thread)
    {
        float4* z = (float4*)sbuf;
        #pragma unroll
        for (int i = 0; i < 2 * 64 * NC / 4 / NT1; i++)
            z[tid + i * NT1] = make_float4(0.f, 0.f, 0.f, 0.f);
    }
    __syncthreads();

    if (tid < NG) {
        slab[tid] = sl64 ? (int)((const long long*)glRaw)[b * NG + tid]
                         : glRaw[b * NG + tid];
        if (v) {
            int pos = __popc(bm & ((1u << (tid & 31)) - 1)) + ((tid >= 32) ? scnt[0] : 0);
            sboxc[pos]  = q;
            sareac[pos] = __fmul_rn(__fsub_rn(q.z, q.x), __fsub_rn(q.w, q.y));
            sgidxc[pos] = tid;
        }
        if (tid == 0) snv = scnt[0] + scnt[1];
    }
    __syncthreads();

    const int a = chunk * NT1 + tid;
    bool posAny = false;

    if (a < NA) {
        float4 p = pd[b * NA + a];
        float parea = __fmul_rn(__fsub_rn(p.z, p.x), __fsub_rn(p.w, p.y));
        float b0n = 0.f, b0d = 1.f, b1n = 0.f, b1d = 1.f;
        int   i0 = 0, i1 = 0;
        const int nv = snv;
        #pragma unroll 4
        for (int j = 0; j < nv; j++) {
            float4 qq = sboxc[j];
            float iw = fmaxf(__fsub_rn(fminf(qq.z, p.z), fmaxf(qq.x, p.x)), 0.f);
            float ih = fmaxf(__fsub_rn(fminf(qq.w, p.w), fmaxf(qq.y, p.y)), 0.f);
            float num = __fmul_rn(iw, ih);
            float den = __fadd_rn(__fsub_rn(__fadd_rn(sareac[j], parea), num), 1e-9f);
            if (__fmul_rn(num, b1d) > __fmul_rn(b1n, den)) {
                int g = sgidxc[j];
                if (__fmul_rn(num, b0d) > __fmul_rn(b0n, den)) {
                    b1n = b0n; b1d = b0d; i1 = i0;
                    b0n = num; b0d = den; i0 = g;
                } else {
                    b1n = num; b1d = den; i1 = g;
                }
            }
        }
        float r0 = __fdiv_rn(b0n, b0d);
        float r1 = __fdiv_rn(b1n, b1d);
        int bi = i0;
        if (r1 == r0 && i1 < i0) bi = i1;
        posAny = r0 > 0.3f;

        const int idx = b * NA + a;
        bool mask = posAny && (svalid[bi] != 0);
        int  lab  = slab[bi];

        outLab[idx] = mask ? (float)lab : (float)NC;
        float4 bx = sbox0[bi];
        outBox[idx] = mask ? bx : make_float4(0.f, 0.f, 0.f, 0.f);
        outFg[idx]  = posAny ? 1.f : 0.f;
        outTgi[idx] = (float)bi;
        spacked[tid] = lab | (mask ? 0x100 : 0);
    }
    int anyBlk = __syncthreads_or(posAny ? 1 : 0);
    if (tid == 0) g_posAnyBlk[b * NCHUNK + chunk] = anyBlk;

    // ----- stream this block's score rows (zeros + one-hot) via TMA bulk ---
    const int remA    = min(NT1, NA - chunk * NT1);
    const int nChunks = (remA + 63) / 64;
    float* gbase = outScores + ((size_t)b * NA + (size_t)chunk * NT1) * NC;
    int prev0 = -1, prev1 = -1;

    for (int c = 0; c < nChunks; c++) {
        int sel = c & 1;
        if (c >= 2 && tid == 0)
            asm volatile("cp.async.bulk.wait_group.read 1;" ::: "memory");
        __syncthreads();                         // buffer[sel] now reusable
        int nA = min(64, remA - c * 64);
        if (tid < 64) {
            int prev = sel ? prev1 : prev0;
            float* buf = sbuf[sel];
            if (prev >= 0) buf[prev] = 0.f;      // clear stale one
            int np = -1;
            if (tid < nA) {
                int p = spacked[c * 64 + tid];
                if (p & 0x100) { np = tid * NC + (p & 0xFF); buf[np] = 1.f; }
            }
            if (sel) prev1 = np; else prev0 = np;
        }
        __syncthreads();
        if (tid == 0) {
            asm volatile("fence.proxy.async.shared::cta;" ::: "memory");
            uint32_t saddr = (uint32_t)__cvta_generic_to_shared(sbuf[sel]);
            float* gdst = gbase + (size_t)c * 64 * NC;
            asm volatile(
                "cp.async.bulk.global.shared::cta.bulk_group [%0], [%1], %2;"
                :: "l"(gdst), "r"(saddr), "r"(nA * NC * 4) : "memory");
            asm volatile("cp.async.bulk.commit_group;" ::: "memory");
        }
    }
    if (tid == 0)
        asm volatile("cp.async.bulk.wait_group 0;" ::: "memory");
    __syncthreads();   // keep block (and its smem) alive until copies complete
}

// ===== fallback pass 1: decide need_fb; per-block top-3 only if needed ====
__global__ __launch_bounds__(NT1)
void k_fb1(const float4* __restrict__ pd,
           const float4* __restrict__ gt,
           const int*    __restrict__ mg,
           const int*    __restrict__ glRaw) {
    const int b   = blockIdx.y;
    const int tid = threadIdx.x;

    int f = (tid < NCHUNK) ? g_posAnyBlk[b * NCHUNK + tid] : 0;
    int anyP = __syncthreads_or(f);
    int hv   = __syncthreads_or((tid < NG) ? (mg[b * NG + tid] != 0) : 0);
    int needFb = (!anyP) && hv;
    if (blockIdx.x == 0 && tid == 0) {
        g_needFb[b] = needFb;
        if (b == 0)
            g_lab64 = ((glRaw[1] | glRaw[3] | glRaw[5] | glRaw[7] |
                        glRaw[9] | glRaw[11]) == 0);
    }
    if (!needFb) return;

    __shared__ float4 sbox[NG];
    __shared__ float  sqa[NG];
    __shared__ float  s0n[NT1], s0d[NT1], s1n[NT1], s1d[NT1], s2n[NT1], s2d[NT1];

    if (tid < NG) {
        float4 q = gt[b * NG + tid];
        if (mg[b * NG + tid] == 0) q = make_float4(0.f, 0.f, 0.f, 0.f);
        sbox[tid] = q;
        sqa[tid]  = __fmul_rn(__fsub_rn(q.z, q.x), __fsub_rn(q.w, q.y));
    }
    __syncthreads();

    const int a = blockIdx.x * NT1 + tid;
    float t0n = -1.f, t0d = 1.f, t1n = -1.f, t1d = 1.f, t2n = -1.f, t2d = 1.f;
    if (a < NA) {
        float4 p = pd[b * NA + a];
        float parea = __fmul_rn(__fsub_rn(p.z, p.x), __fsub_rn(p.w, p.y));
        for (int g = 0; g < NG; g++) {
            float4 q = sbox[g];
            float iw = fmaxf(__fsub_rn(fminf(q.z, p.z), fmaxf(q.x, p.x)), 0.f);
            float ih = fmaxf(__fsub_rn(fminf(q.w, p.w), fmaxf(q.y, p.y)), 0.f);
            float num = __fmul_rn(iw, ih);
            float den = __fadd_rn(__fsub_rn(__fadd_rn(sqa[g], parea), num), 1e-9f);
            ins3(num, den, t0n, t0d, t1n, t1d, t2n, t2d);
        }
    }
    s0n[tid] = t0n; s0d[tid] = t0d;
    s1n[tid] = t1n; s1d[tid] = t1d;
    s2n[tid] = t2n; s2d[tid] = t2d;
    __syncthreads();
    for (int off = NT1 / 2; off > 0; off >>= 1) {
        if (tid < off) {
            float m0n = s0n[tid], m0d = s0d[tid], m1n = s1n[tid], m1d = s1d[tid],
                  m2n = s2n[tid], m2d = s2d[tid];
            int j = tid + off;
            ins3(s0n[j], s0d[j], m0n, m0d, m1n, m1d, m2n, m2d);
            ins3(s1n[j], s1d[j], m0n, m0d, m1n, m1d, m2n, m2d);
            ins3(s2n[j], s2d[j], m0n, m0d, m1n, m1d, m2n, m2d);
            s0n[tid] = m0n; s0d[tid] = m0d;
            s1n[tid] = m1n; s1d[tid] = m1d;
            s2n[tid] = m2n; s2d[tid] = m2d;
        }
        __syncthreads();
    }
    if (tid == 0) {
        int o = (b * NCHUNK + blockIdx.x) * 6;
        g_top3[o + 0] = s0n[0]; g_top3[o + 1] = s0d[0];
        g_top3[o + 2] = s1n[0]; g_top3[o + 3] = s1d[0];
        g_top3[o + 4] = s2n[0]; g_top3[o + 5] = s2d[0];
    }
}

// ===== fallback pass 2: merge -> min_iou ===================================
__global__ void k_fb2() {
    const int b = blockIdx.x, tid = threadIdx.x;   // 128 threads
    if (!g_needFb[b]) return;
    float t0n = -1.f, t0d = 1.f, t1n = -1.f, t1d = 1.f, t2n = -1.f, t2d = 1.f;
    for (int i = tid; i < NCHUNK; i += 128) {
        const float* p = &g_top3[(b * NCHUNK + i) * 6];
        ins3(p[0], p[1], t0n, t0d, t1n, t1d, t2n, t2d);
        ins3(p[2], p[3], t0n, t0d, t1n, t1d, t2n, t2d);
        ins3(p[4], p[5], t0n, t0d, t1n, t1d, t2n, t2d);
    }
    __shared__ float s0n[128], s0d[128], s1n[128], s1d[128], s2n[128], s2d[128];
    s0n[tid] = t0n; s0d[tid] = t0d;
    s1n[tid] = t1n; s1d[tid] = t1d;
    s2n[tid] = t2n; s2d[tid] = t2d;
    __syncthreads();
    for (int off = 64; off > 0; off >>= 1) {
        if (tid < off) {
            float m0n = s0n[tid], m0d = s0d[tid], m1n = s1n[tid], m1d = s1d[tid],
                  m2n = s2n[tid], m2d = s2d[tid];
            int j = tid + off;
            ins3(s0n[j], s0d[j], m0n, m0d, m1n, m1d, m2n, m2d);
            ins3(s1n[j], s1d[j], m0n, m0d, m1n, m1d, m2n, m2d);
            ins3(s2n[j], s2d[j], m0n, m0d, m1n, m1d, m2n, m2d);
            s0n[tid] = m0n; s0d[tid] = m0d;
            s1n[tid] = m1n; s1d[tid] = m1d;
            s2n[tid] = m2n; s2d[tid] = m2d;
        }
        __syncthreads();
    }
    if (tid == 0) g_minIou[b] = __fdiv_rn(s2n[0], s2d[0]);
}

// ===== fallback fix: recompute + rewrite outputs for flagged batches =======
__global__ __launch_bounds__(NT1)
void k_fbfix(const float4* __restrict__ pd,
             const float4* __restrict__ gt,
             const int*    __restrict__ glRaw,
             const int*    __restrict__ mg,
             float*  __restrict__ outLab,
             float4* __restrict__ outBox,
             float*  __restrict__ outFg,
             float*  __restrict__ outTgi,
             float*  __restrict__ outScores) {
    const int b = blockIdx.y;
    if (!g_needFb[b]) return;
    const int tid = threadIdx.x;

    __shared__ float4 sbox[NG];
    __shared__ float  sqa[NG];
    if (tid < NG) {
        float4 q = gt[b * NG + tid];
        if (mg[b * NG + tid] == 0) q = make_float4(0.f, 0.f, 0.f, 0.f);
        sbox[tid] = q;
        sqa[tid]  = __fmul_rn(__fsub_rn(q.z, q.x), __fsub_rn(q.w, q.y));
    }
    __syncthreads();

    const int a = blockIdx.x * NT1 + tid;
    if (a >= NA) return;

    float4 p = pd[b * NA + a];
    float parea = __fmul_rn(__fsub_rn(p.z, p.x), __fsub_rn(p.w, p.y));
    float b0n = 0.f, b0d = 1.f, b1n = 0.f, b1d = 1.f;
    int   i0 = 0, i1 = 0;
    for (int g = 0; g < NG; g++) {
        float4 q = sbox[g];
        float iw = fmaxf(__fsub_rn(fminf(q.z, p.z), fmaxf(q.x, p.x)), 0.f);
        float ih = fmaxf(__fsub_rn(fminf(q.w, p.w), fmaxf(q.y, p.y)), 0.f);
        float num = __fmul_rn(iw, ih);
        float den = __fadd_rn(__fsub_rn(__fadd_rn(sqa[g], parea), num), 1e-9f);
        if (__fmul_rn(num, b1d) > __fmul_rn(b1n, den)) {
            if (__fmul_rn(num, b0d) > __fmul_rn(b0n, den)) {
                b1n = b0n; b1d = b0d; i1 = i0;
                b0n = num; b0d = den; i0 = g;
            } else {
                b1n = num; b1d = den; i1 = g;
            }
        }
    }
    float r0 = __fdiv_rn(b0n, b0d);
    float r1 = __fdiv_rn(b1n, b1d);
    int tgi = i0;
    if (r1 == r0 && i1 < i0) tgi = i1;

    const int idx = b * NA + a;
    bool fg   = r0 >= g_minIou[b];
    bool va   = mg[b * NG + tgi] != 0;
    bool mask = fg && va;
    int  lab  = g_lab64 ? (int)((const long long*)glRaw)[b * NG + tgi]
                        : glRaw[b * NG + tgi];

    outLab[idx] = mask ? (float)lab : (float)NC;
    float4 bx = gt[b * NG + tgi];
    outBox[idx] = mask ? bx : make_float4(0.f, 0.f, 0.f, 0.f);
    outFg[idx]  = fg ? 1.f : 0.f;
    outTgi[idx] = (float)tgi;
    if (mask) outScores[(size_t)idx * NC + lab] = 1.f;  // rows are all-zero here
}

// ------------------------------ entry point -------------------------------
// inputs: 0 pd_scores, 1 pd_bboxes, 2 anc_points, 3 gt_labels, 4 gt_bboxes, 5 mask_gt
// output: float32 concat [labels | bboxes | scores | fg_mask | tgi]
extern "C" void kernel_launch(void* const* d_in, const int* in_sizes, int n_in,
                              void* d_out, int out_size) {
    const float4* pd = (const float4*)d_in[1];
    const int*    gl = (const int*)d_in[3];
    const float4* gt = (const float4*)d_in[4];
    const int*    mg = (const int*)d_in[5];

    float* out = (float*)d_out;
    const size_t E = (size_t)BS * NA;
    float*  outLab    = out;
    float4* outBox    = (float4*)(out + E);
    float*  outScores = out + E * 5;
    float*  outFg     = out + E * 85;
    float*  outTgi    = out + E * 86;

    k1f<<<NCOMP, NT1>>>(pd, gt, mg, gl, outLab, outBox, outFg, outTgi, outScores);

    dim3 gfb(NCHUNK, BS);
    k_fb1<<<gfb, NT1>>>(pd, gt, mg, gl);
    k_fb2<<<BS, 128>>>();
    k_fbfix<<<gfb, NT1>>>(pd, gt, gl, mg, outLab, outBox, outFg, outTgi, outScores);
}